// round 2
// baseline (speedup 1.0000x reference)
#include <cuda_runtime.h>
#include <cuda_fp16.h>
#include <mma.h>

using namespace nvcuda;

// Problem dims
#define BATCH 256
#define J_DIM 1024            // neurons (reduction of GEMM1)
#define K_DIM 1024            // n_feat  (M of GEMM1)
#define L_DIM 256             // in_dim
#define M_DIM 128             // out_dim (N of GEMM2)
#define LM    (L_DIM * M_DIM) // 32768   (N of GEMM1)
#define R_DIM (K_DIM * L_DIM) // 262144  (reduction of GEMM2)

// Tiling
#define BM 128
#define BN 128
#define BK 32
#define LDA_S (BK + 8)   // 40 halves, 80B rows (16B-aligned chunks ok)
#define LDB_S (BN + 8)   // 136 halves, 272B rows
#define NSPLIT 128
#define SPLIT_LEN (R_DIM / NSPLIT)  // 2048

// Scratch (static device globals — no allocation APIs allowed)
__device__ __half g_GT[(size_t)K_DIM * J_DIM];   //  2 MB : G^T in fp16, (k, j)
__device__ __half g_D16[(size_t)J_DIM * LM];     // 67 MB : (v - w) fp16, (j, l*128+m)
__device__ __half g_E[(size_t)K_DIM * LM];       // 67 MB : E fp16, ((k*256+l)*128+m)

// ---------------------------------------------------------------------------
// Convert kernels
// ---------------------------------------------------------------------------

// G (j,k) fp32 -> g_GT (k,j) fp16, tiled transpose
__global__ void conv_GT_kernel(const float* __restrict__ G) {
    __shared__ float t[32][33];
    int jx = blockIdx.y * 32 + threadIdx.y;   // j
    int kx = blockIdx.x * 32 + threadIdx.x;   // k
    t[threadIdx.y][threadIdx.x] = G[jx * K_DIM + kx];
    __syncthreads();
    int ko = blockIdx.x * 32 + threadIdx.y;
    int jo = blockIdx.y * 32 + threadIdx.x;
    g_GT[(size_t)ko * J_DIM + jo] = __float2half(t[threadIdx.x][threadIdx.y]);
}

// g_D16 = fp16(v - w), elementwise, 4 elems/thread
__global__ void conv_D_kernel(const float* __restrict__ v, const float* __restrict__ w) {
    size_t i = (size_t)blockIdx.x * blockDim.x + threadIdx.x;  // index in float4 units
    float4 a = reinterpret_cast<const float4*>(v)[i];
    float4 b = reinterpret_cast<const float4*>(w)[i];
    __half2 lo = __floats2half2_rn(a.x - b.x, a.y - b.y);
    __half2 hi = __floats2half2_rn(a.z - b.z, a.w - b.w);
    __half2* dst = reinterpret_cast<__half2*>(&g_D16[i * 4]);
    dst[0] = lo;
    dst[1] = hi;
}

__global__ void zero_kernel(float* __restrict__ o) {
    int i = blockIdx.x * 256 + threadIdx.x;
    o[i] = 0.0f;
}

// ---------------------------------------------------------------------------
// GEMM1: E[k, lm] = sum_j GT[k, j] * D16[j, lm]
// M = K_DIM = 1024, N = LM = 32768, K = J_DIM = 1024
// grid (LM/BN = 256, K_DIM/BM = 8), 256 threads (8 warps, 4x2, 32x64 each)
// ---------------------------------------------------------------------------
__global__ __launch_bounds__(256) void gemm1_kernel() {
    __shared__ __half As[BM * LDA_S];
    __shared__ __half Bs[BK * LDB_S];
    __shared__ float  stage[8][256];

    const int tid  = threadIdx.x;
    const int warp = tid >> 5;
    const int lane = tid & 31;
    const int wm   = warp >> 1;   // 0..3
    const int wn   = warp & 1;    // 0..1
    const int mBase = blockIdx.y * BM;
    const int nBase = blockIdx.x * BN;

    wmma::fragment<wmma::accumulator, 16, 16, 16, float> acc[2][4];
#pragma unroll
    for (int i = 0; i < 2; i++)
#pragma unroll
        for (int j = 0; j < 4; j++)
            wmma::fill_fragment(acc[i][j], 0.0f);

    for (int k0 = 0; k0 < J_DIM; k0 += BK) {
        // A tile: 128x32 halves = 512 uint4
#pragma unroll
        for (int c = tid; c < 512; c += 256) {
            int row = c >> 2, cc = c & 3;
            *reinterpret_cast<uint4*>(&As[row * LDA_S + cc * 8]) =
                *reinterpret_cast<const uint4*>(&g_GT[(size_t)(mBase + row) * J_DIM + k0 + cc * 8]);
        }
        // B tile: 32x128 halves = 512 uint4
#pragma unroll
        for (int c = tid; c < 512; c += 256) {
            int row = c >> 4, cc = c & 15;
            *reinterpret_cast<uint4*>(&Bs[row * LDB_S + cc * 8]) =
                *reinterpret_cast<const uint4*>(&g_D16[(size_t)(k0 + row) * LM + nBase + cc * 8]);
        }
        __syncthreads();
#pragma unroll
        for (int kk = 0; kk < BK; kk += 16) {
            wmma::fragment<wmma::matrix_a, 16, 16, 16, __half, wmma::row_major> af[2];
            wmma::fragment<wmma::matrix_b, 16, 16, 16, __half, wmma::row_major> bf[4];
#pragma unroll
            for (int i = 0; i < 2; i++)
                wmma::load_matrix_sync(af[i], &As[(wm * 32 + i * 16) * LDA_S + kk], LDA_S);
#pragma unroll
            for (int j = 0; j < 4; j++)
                wmma::load_matrix_sync(bf[j], &Bs[kk * LDB_S + wn * 64 + j * 16], LDB_S);
#pragma unroll
            for (int i = 0; i < 2; i++)
#pragma unroll
                for (int j = 0; j < 4; j++)
                    wmma::mma_sync(acc[i][j], af[i], bf[j], acc[i][j]);
        }
        __syncthreads();
    }

    // Epilogue: stage each 16x16 frag per-warp, convert to fp16, write E
    const int r  = lane >> 1;
    const int c8 = (lane & 1) * 8;
#pragma unroll
    for (int i = 0; i < 2; i++)
#pragma unroll
        for (int j = 0; j < 4; j++) {
            wmma::store_matrix_sync(stage[warp], acc[i][j], 16, wmma::mem_row_major);
            __syncwarp();
            const float* sp = &stage[warp][r * 16 + c8];
            __half2 p0 = __floats2half2_rn(sp[0], sp[1]);
            __half2 p1 = __floats2half2_rn(sp[2], sp[3]);
            __half2 p2 = __floats2half2_rn(sp[4], sp[5]);
            __half2 p3 = __floats2half2_rn(sp[6], sp[7]);
            size_t off = (size_t)(mBase + wm * 32 + i * 16 + r) * LM
                       + nBase + wn * 64 + j * 16 + c8;
            __half2* dst = reinterpret_cast<__half2*>(&g_E[off]);
            dst[0] = p0; dst[1] = p1; dst[2] = p2; dst[3] = p3;
            __syncwarp();
        }
}

// ---------------------------------------------------------------------------
// GEMM2: out[i, m] += sum_r fp16(x[i, r]) * E[r, m]
// M = 256, N = 128, K = 262144, split-K over NSPLIT chunks + float atomics
// grid (NSPLIT, BATCH/BM = 2), 256 threads
// ---------------------------------------------------------------------------
__global__ __launch_bounds__(256) void gemm2_kernel(const float* __restrict__ X,
                                                    float* __restrict__ out) {
    __shared__ __half As[BM * LDA_S];
    __shared__ __half Bs[BK * LDB_S];
    __shared__ float  stage[8][256];

    const int tid  = threadIdx.x;
    const int warp = tid >> 5;
    const int lane = tid & 31;
    const int wm   = warp >> 1;
    const int wn   = warp & 1;
    const int mBase  = blockIdx.y * BM;
    const int kStart = blockIdx.x * SPLIT_LEN;

    wmma::fragment<wmma::accumulator, 16, 16, 16, float> acc[2][4];
#pragma unroll
    for (int i = 0; i < 2; i++)
#pragma unroll
        for (int j = 0; j < 4; j++)
            wmma::fill_fragment(acc[i][j], 0.0f);

    for (int k0 = kStart; k0 < kStart + SPLIT_LEN; k0 += BK) {
        // A tile: x fp32 128x32 -> fp16 on the fly (2048 float2 chunks)
#pragma unroll
        for (int c = tid; c < 2048; c += 256) {
            int row = c >> 4, cc = c & 15;
            float2 v2 = *reinterpret_cast<const float2*>(
                &X[(size_t)(mBase + row) * R_DIM + k0 + cc * 2]);
            *reinterpret_cast<__half2*>(&As[row * LDA_S + cc * 2]) =
                __floats2half2_rn(v2.x, v2.y);
        }
        // B tile: E rows k0..k0+31, all 128 cols
#pragma unroll
        for (int c = tid; c < 512; c += 256) {
            int row = c >> 4, cc = c & 15;
            *reinterpret_cast<uint4*>(&Bs[row * LDB_S + cc * 8]) =
                *reinterpret_cast<const uint4*>(&g_E[(size_t)(k0 + row) * M_DIM + cc * 8]);
        }
        __syncthreads();
#pragma unroll
        for (int kk = 0; kk < BK; kk += 16) {
            wmma::fragment<wmma::matrix_a, 16, 16, 16, __half, wmma::row_major> af[2];
            wmma::fragment<wmma::matrix_b, 16, 16, 16, __half, wmma::row_major> bf[4];
#pragma unroll
            for (int i = 0; i < 2; i++)
                wmma::load_matrix_sync(af[i], &As[(wm * 32 + i * 16) * LDA_S + kk], LDA_S);
#pragma unroll
            for (int j = 0; j < 4; j++)
                wmma::load_matrix_sync(bf[j], &Bs[kk * LDB_S + wn * 64 + j * 16], LDB_S);
#pragma unroll
            for (int i = 0; i < 2; i++)
#pragma unroll
                for (int j = 0; j < 4; j++)
                    wmma::mma_sync(acc[i][j], af[i], bf[j], acc[i][j]);
        }
        __syncthreads();
    }

    // Epilogue: atomic accumulate split-K partials into out (pre-zeroed)
    const int r  = lane >> 1;
    const int c8 = (lane & 1) * 8;
#pragma unroll
    for (int i = 0; i < 2; i++)
#pragma unroll
        for (int j = 0; j < 4; j++) {
            wmma::store_matrix_sync(stage[warp], acc[i][j], 16, wmma::mem_row_major);
            __syncwarp();
            const float* sp = &stage[warp][r * 16 + c8];
            int gm = mBase + wm * 32 + i * 16 + r;
            int gn = wn * 64 + j * 16 + c8;
#pragma unroll
            for (int t = 0; t < 8; t++)
                atomicAdd(&out[gm * M_DIM + gn + t], sp[t]);
            __syncwarp();
        }
}

// ---------------------------------------------------------------------------
// Launch
// ---------------------------------------------------------------------------
extern "C" void kernel_launch(void* const* d_in, const int* in_sizes, int n_in,
                              void* d_out, int out_size) {
    const float* x = (const float*)d_in[0];   // (256, 1024, 256)
    const float* G = (const float*)d_in[1];   // (1024, 1024)
    const float* v = (const float*)d_in[2];   // (1024, 256, 128)
    const float* w = (const float*)d_in[3];   // (1024, 256, 128)
    float* out = (float*)d_out;               // (256, 128)

    conv_GT_kernel<<<dim3(32, 32), dim3(32, 32)>>>(G);
    conv_D_kernel<<<(J_DIM * (size_t)LM) / (4 * 256), 256>>>(v, w);
    zero_kernel<<<(BATCH * M_DIM) / 256, 256>>>(out);
    gemm1_kernel<<<dim3(LM / BN, K_DIM / BM), 256>>>();
    gemm2_kernel<<<dim3(NSPLIT, BATCH / BM), 256>>>(x, out);
}

// round 5
// speedup vs baseline: 1.1351x; 1.1351x over previous
#include <cuda_runtime.h>
#include <cuda_fp16.h>
#include <mma.h>
#include <cstdint>

using namespace nvcuda;

// Problem dims
#define BATCH 256
#define J_DIM 1024            // neurons (reduction of GEMM1)
#define K_DIM 1024            // n_feat  (M of GEMM1)
#define L_DIM 256             // in_dim
#define M_DIM 128             // out_dim (N of GEMM2)
#define LM    (L_DIM * M_DIM) // 32768   (N of GEMM1)
#define R_DIM (K_DIM * L_DIM) // 262144  (reduction of GEMM2)

// GEMM2 (WMMA) tiling
#define BM 128
#define BN 128
#define BK 32
#define LDA_S (BK + 8)
#define LDB_S (BN + 8)
#define NSPLIT 128
#define SPLIT_LEN (R_DIM / NSPLIT)  // 2048

// GEMM1 tiling: CTA 128x256x64, 8 warps of 64x64
#define BM1 128
#define BN1 256
#define BK1 64
#define LDA1 72                        // halves (144 B rows, 16B-aligned)
#define LDB1 264                       // halves (528 B rows, 16B-aligned)
#define NST1 3
#define A1_BYTES (BM1 * LDA1 * 2)      // 18432
#define B1_BYTES (BK1 * LDB1 * 2)      // 33792
#define STG1 (A1_BYTES + B1_BYTES)     // 52224
#define SMEM1 (NST1 * STG1)            // 156672
#define NCH1 (J_DIM / BK1)             // 16

// Scratch (static device globals — no allocation APIs allowed)
__device__ __half g_GT[(size_t)K_DIM * J_DIM];   //  2 MB : G^T fp16, (k, j)
__device__ __half g_D16[(size_t)J_DIM * LM];     // 64 MB : (v-w) fp16, (j, lm)
__device__ __half g_E[(size_t)K_DIM * LM];       // 64 MB : E fp16, (r, m)

// ---------------------------------------------------------------------------
// Helpers
// ---------------------------------------------------------------------------
__device__ __forceinline__ uint32_t smem_u32(const void* p) {
    uint32_t a;
    asm("{ .reg .u64 t; cvta.to.shared.u64 t, %1; cvt.u32.u64 %0, t; }" : "=r"(a) : "l"(p));
    return a;
}
#define CP_ASYNC16(dst, src) \
    asm volatile("cp.async.cg.shared.global [%0], [%1], 16;" :: "r"(dst), "l"(src))
#define CP_COMMIT() asm volatile("cp.async.commit_group;" ::: "memory")
#define CP_WAIT(n)  asm volatile("cp.async.wait_group %0;" :: "n"(n) : "memory")

// ---------------------------------------------------------------------------
// Convert kernels
// ---------------------------------------------------------------------------

// G (j,k) fp32 -> g_GT (k,j) fp16
__global__ void conv_GT_kernel(const float* __restrict__ G) {
    __shared__ float t[32][33];
    int jx = blockIdx.y * 32 + threadIdx.y;
    int kx = blockIdx.x * 32 + threadIdx.x;
    t[threadIdx.y][threadIdx.x] = G[jx * K_DIM + kx];
    __syncthreads();
    int ko = blockIdx.x * 32 + threadIdx.y;
    int jo = blockIdx.y * 32 + threadIdx.x;
    g_GT[(size_t)ko * J_DIM + jo] = __float2half(t[threadIdx.x][threadIdx.y]);
}

// g_D16 = fp16(v - w), elementwise, 4 elems/thread (streaming, coalesced)
__global__ void conv_D_kernel(const float* __restrict__ v, const float* __restrict__ w) {
    size_t i = (size_t)blockIdx.x * blockDim.x + threadIdx.x;  // float4 units
    float4 a = reinterpret_cast<const float4*>(v)[i];
    float4 b = reinterpret_cast<const float4*>(w)[i];
    __half2 lo = __floats2half2_rn(a.x - b.x, a.y - b.y);
    __half2 hi = __floats2half2_rn(a.z - b.z, a.w - b.w);
    __half2* dst = reinterpret_cast<__half2*>(&g_D16[i * 4]);
    dst[0] = lo;
    dst[1] = hi;
}

__global__ void zero_kernel(float* __restrict__ o) {
    int i = blockIdx.x * 256 + threadIdx.x;
    o[i] = 0.0f;
}

// ---------------------------------------------------------------------------
// GEMM1: E[k, n] = sum_j GT[k, j] * D16[j, n]
// CTA 128x256, BK=64, 3-stage cp.async pipeline, 8 warps of 64x64.
// grid (K_DIM/128 = 8, LM/256 = 128), 256 threads.
// ---------------------------------------------------------------------------
__global__ __launch_bounds__(256) void gemm1_kernel2() {
    extern __shared__ char sm[];

    const int tid  = threadIdx.x;
    const int warp = tid >> 5;
    const int lane = tid & 31;
    const int wm   = warp >> 2;   // 0..1  (64-row slab)
    const int wn   = warp & 3;    // 0..3  (64-col slab)
    const int mBase = blockIdx.x * BM1;
    const int nBase = blockIdx.y * BN1;

    const uint32_t smem_base = smem_u32(sm);

    wmma::fragment<wmma::accumulator, 16, 16, 16, float> acc[4][4];
#pragma unroll
    for (int i = 0; i < 4; i++)
#pragma unroll
        for (int j = 0; j < 4; j++)
            wmma::fill_fragment(acc[i][j], 0.0f);

    // Stage fill via cp.async (16B units). A: 128 rows x 8 units. B: 64 rows x 32 units.
    auto fill = [&](int s, int chunk) {
        uint32_t a_base = smem_base + s * STG1;
        uint32_t b_base = a_base + A1_BYTES;
#pragma unroll
        for (int u = tid; u < 1024; u += 256) {
            int row = u >> 3, c = u & 7;
            uint32_t dst = a_base + row * (LDA1 * 2) + c * 16;
            const void* src = &g_GT[(size_t)(mBase + row) * J_DIM + chunk * BK1 + c * 8];
            CP_ASYNC16(dst, src);
        }
#pragma unroll
        for (int u = tid; u < 2048; u += 256) {
            int row = u >> 5, c = u & 31;
            uint32_t dst = b_base + row * (LDB1 * 2) + c * 16;
            const void* src = &g_D16[(size_t)(chunk * BK1 + row) * LM + nBase + c * 8];
            CP_ASYNC16(dst, src);
        }
        CP_COMMIT();
    };

#pragma unroll
    for (int s = 0; s < NST1; s++) fill(s, s);

    for (int i = 0; i < NCH1; i++) {
        int s = i % NST1;
        if (i < NCH1 - 2)       CP_WAIT(2);
        else if (i == NCH1 - 2) CP_WAIT(1);
        else                    CP_WAIT(0);
        __syncthreads();

        const __half* As = reinterpret_cast<const __half*>(sm + s * STG1);
        const __half* Bs = reinterpret_cast<const __half*>(sm + s * STG1 + A1_BYTES);

#pragma unroll
        for (int kk = 0; kk < BK1 / 16; kk++) {
            wmma::fragment<wmma::matrix_a, 16, 16, 16, __half, wmma::row_major> af[4];
#pragma unroll
            for (int ii = 0; ii < 4; ii++)
                wmma::load_matrix_sync(af[ii],
                    &As[(wm * 64 + ii * 16) * LDA1 + kk * 16], LDA1);
#pragma unroll
            for (int j = 0; j < 4; j++) {
                wmma::fragment<wmma::matrix_b, 16, 16, 16, __half, wmma::row_major> bf;
                wmma::load_matrix_sync(bf,
                    &Bs[(kk * 16) * LDB1 + wn * 64 + j * 16], LDB1);
#pragma unroll
                for (int ii = 0; ii < 4; ii++)
                    wmma::mma_sync(acc[ii][j], af[ii], bf, acc[ii][j]);
            }
        }
        __syncthreads();
        if (i + NST1 < NCH1) fill(s, i + NST1);
    }

    __syncthreads();   // all warps done with smem; reuse stage 0 as epilogue staging

    // Epilogue: per-warp 16x16 staging, fp32 -> fp16, 16B stores to g_E
    float* stg = reinterpret_cast<float*>(sm) + warp * 256;
    const int r  = lane >> 1;
    const int c8 = (lane & 1) * 8;
#pragma unroll
    for (int i = 0; i < 4; i++)
#pragma unroll
        for (int j = 0; j < 4; j++) {
            wmma::store_matrix_sync(stg, acc[i][j], 16, wmma::mem_row_major);
            __syncwarp();
            const float* sp = &stg[r * 16 + c8];
            __half2 h[4];
#pragma unroll
            for (int p = 0; p < 4; p++)
                h[p] = __floats2half2_rn(sp[2 * p], sp[2 * p + 1]);
            size_t off = (size_t)(mBase + wm * 64 + i * 16 + r) * LM
                       + nBase + wn * 64 + j * 16 + c8;
            *reinterpret_cast<uint4*>(&g_E[off]) = *reinterpret_cast<uint4*>(h);
            __syncwarp();
        }
}

// ---------------------------------------------------------------------------
// GEMM2 (WMMA): out[i, m] += sum_r fp16(x[i, r]) * E[r, m]
// ---------------------------------------------------------------------------
__global__ __launch_bounds__(256) void gemm2_kernel(const float* __restrict__ X,
                                                    float* __restrict__ out) {
    __shared__ __half As[BM * LDA_S];
    __shared__ __half Bs[BK * LDB_S];
    __shared__ float  stage[8][256];

    const int tid  = threadIdx.x;
    const int warp = tid >> 5;
    const int lane = tid & 31;
    const int wm   = warp >> 1;
    const int wn   = warp & 1;
    const int mBase  = blockIdx.y * BM;
    const int kStart = blockIdx.x * SPLIT_LEN;

    wmma::fragment<wmma::accumulator, 16, 16, 16, float> acc[2][4];
#pragma unroll
    for (int i = 0; i < 2; i++)
#pragma unroll
        for (int j = 0; j < 4; j++)
            wmma::fill_fragment(acc[i][j], 0.0f);

    for (int k0 = kStart; k0 < kStart + SPLIT_LEN; k0 += BK) {
#pragma unroll
        for (int c = tid; c < 2048; c += 256) {
            int row = c >> 4, cc = c & 15;
            float2 v2 = *reinterpret_cast<const float2*>(
                &X[(size_t)(mBase + row) * R_DIM + k0 + cc * 2]);
            *reinterpret_cast<__half2*>(&As[row * LDA_S + cc * 2]) =
                __floats2half2_rn(v2.x, v2.y);
        }
#pragma unroll
        for (int c = tid; c < 512; c += 256) {
            int row = c >> 4, cc = c & 15;
            *reinterpret_cast<uint4*>(&Bs[row * LDB_S + cc * 8]) =
                *reinterpret_cast<const uint4*>(&g_E[(size_t)(k0 + row) * M_DIM + cc * 8]);
        }
        __syncthreads();
#pragma unroll
        for (int kk = 0; kk < BK; kk += 16) {
            wmma::fragment<wmma::matrix_a, 16, 16, 16, __half, wmma::row_major> af[2];
            wmma::fragment<wmma::matrix_b, 16, 16, 16, __half, wmma::row_major> bf[4];
#pragma unroll
            for (int i = 0; i < 2; i++)
                wmma::load_matrix_sync(af[i], &As[(wm * 32 + i * 16) * LDA_S + kk], LDA_S);
#pragma unroll
            for (int j = 0; j < 4; j++)
                wmma::load_matrix_sync(bf[j], &Bs[kk * LDB_S + wn * 64 + j * 16], LDB_S);
#pragma unroll
            for (int i = 0; i < 2; i++)
#pragma unroll
                for (int j = 0; j < 4; j++)
                    wmma::mma_sync(acc[i][j], af[i], bf[j], acc[i][j]);
        }
        __syncthreads();
    }

    const int r  = lane >> 1;
    const int c8 = (lane & 1) * 8;
#pragma unroll
    for (int i = 0; i < 2; i++)
#pragma unroll
        for (int j = 0; j < 4; j++) {
            wmma::store_matrix_sync(stage[warp], acc[i][j], 16, wmma::mem_row_major);
            __syncwarp();
            const float* sp = &stage[warp][r * 16 + c8];
            int gm = mBase + wm * 32 + i * 16 + r;
            int gn = wn * 64 + j * 16 + c8;
#pragma unroll
            for (int t = 0; t < 8; t++)
                atomicAdd(&out[gm * M_DIM + gn + t], sp[t]);
            __syncwarp();
        }
}

// ---------------------------------------------------------------------------
// Launch
// ---------------------------------------------------------------------------
extern "C" void kernel_launch(void* const* d_in, const int* in_sizes, int n_in,
                              void* d_out, int out_size) {
    const float* x = (const float*)d_in[0];   // (256, 1024, 256)
    const float* G = (const float*)d_in[1];   // (1024, 1024)
    const float* v = (const float*)d_in[2];   // (1024, 256, 128)
    const float* w = (const float*)d_in[3];   // (1024, 256, 128)
    float* out = (float*)d_out;               // (256, 128)

    // Idempotent, non-stream API call: capture-legal, no static guards.
    cudaFuncSetAttribute(gemm1_kernel2,
                         cudaFuncAttributeMaxDynamicSharedMemorySize, SMEM1);

    conv_GT_kernel<<<dim3(32, 32), dim3(32, 32)>>>(G);
    conv_D_kernel<<<(J_DIM * (size_t)LM) / (4 * 256), 256>>>(v, w);
    zero_kernel<<<(BATCH * M_DIM) / 256, 256>>>(out);
    gemm1_kernel2<<<dim3(K_DIM / BM1, LM / BN1), 256, SMEM1>>>();
    gemm2_kernel<<<dim3(NSPLIT, BATCH / BM), 256>>>(x, out);
}

// round 9
// speedup vs baseline: 1.1756x; 1.0356x over previous
#include <cuda_runtime.h>
#include <cuda_fp16.h>
#include <mma.h>
#include <cstdint>

using namespace nvcuda;

// Problem dims
#define BATCH 256
#define J_DIM 1024            // neurons (reduction of GEMM1)
#define K_DIM 1024            // n_feat  (M of GEMM1)
#define L_DIM 256             // in_dim
#define M_DIM 128             // out_dim (N of GEMM2)
#define LM    (L_DIM * M_DIM) // 32768   (N of GEMM1)
#define R_DIM (K_DIM * L_DIM) // 262144  (reduction of GEMM2)

// GEMM2 (WMMA) tiling
#define BM 128
#define BN 128
#define BK 32
#define LDA_S (BK + 8)
#define LDB_S (BN + 8)
#define NSPLIT 128
#define SPLIT_LEN (R_DIM / NSPLIT)  // 2048

// GEMM1 tiling: CTA 128x128x64, 8 warps of 64x32, 2 CTAs/SM
#define BM1 128
#define BN1 128
#define BK1 64
#define LDA1 72                        // halves (144 B rows)
#define LDB1 136                       // halves (272 B rows)
#define NST1 3
#define A1_BYTES (BM1 * LDA1 * 2)      // 18432
#define B1_BYTES (BK1 * LDB1 * 2)      // 17408
#define STG1 (A1_BYTES + B1_BYTES)     // 35840
#define SMEM1 (NST1 * STG1)            // 107520 (x2 CTAs = 215040 <= 228KB/SM)
#define NCH1 (J_DIM / BK1)             // 16

// Scratch (static device globals — no allocation APIs allowed)
__device__ __half g_GT[(size_t)K_DIM * J_DIM];   //  2 MB : G^T fp16, (k, j)
__device__ __half g_D16[(size_t)J_DIM * LM];     // 64 MB : (v-w) fp16, (j, lm)
__device__ __half g_E[(size_t)K_DIM * LM];       // 64 MB : E fp16, (r, m)

// ---------------------------------------------------------------------------
// Helpers
// ---------------------------------------------------------------------------
__device__ __forceinline__ uint32_t smem_u32(const void* p) {
    uint32_t a;
    asm("{ .reg .u64 t; cvta.to.shared.u64 t, %1; cvt.u32.u64 %0, t; }" : "=r"(a) : "l"(p));
    return a;
}
#define CP_ASYNC16(dst, src) \
    asm volatile("cp.async.cg.shared.global [%0], [%1], 16;" :: "r"(dst), "l"(src))
#define CP_COMMIT() asm volatile("cp.async.commit_group;" ::: "memory")
#define CP_WAIT(n)  asm volatile("cp.async.wait_group %0;" :: "n"(n) : "memory")

// ---------------------------------------------------------------------------
// Convert kernels
// ---------------------------------------------------------------------------

// G (j,k) fp32 -> g_GT (k,j) fp16
__global__ void conv_GT_kernel(const float* __restrict__ G) {
    __shared__ float t[32][33];
    int jx = blockIdx.y * 32 + threadIdx.y;
    int kx = blockIdx.x * 32 + threadIdx.x;
    t[threadIdx.y][threadIdx.x] = G[jx * K_DIM + kx];
    __syncthreads();
    int ko = blockIdx.x * 32 + threadIdx.y;
    int jo = blockIdx.y * 32 + threadIdx.x;
    g_GT[(size_t)ko * J_DIM + jo] = __float2half(t[threadIdx.x][threadIdx.y]);
}

// g_D16 = fp16(v - w), elementwise, 4 elems/thread (streaming, coalesced)
__global__ void conv_D_kernel(const float* __restrict__ v, const float* __restrict__ w) {
    size_t i = (size_t)blockIdx.x * blockDim.x + threadIdx.x;  // float4 units
    float4 a = reinterpret_cast<const float4*>(v)[i];
    float4 b = reinterpret_cast<const float4*>(w)[i];
    __half2 lo = __floats2half2_rn(a.x - b.x, a.y - b.y);
    __half2 hi = __floats2half2_rn(a.z - b.z, a.w - b.w);
    __half2* dst = reinterpret_cast<__half2*>(&g_D16[i * 4]);
    dst[0] = lo;
    dst[1] = hi;
}

__global__ void zero_kernel(float* __restrict__ o) {
    int i = blockIdx.x * 256 + threadIdx.x;
    o[i] = 0.0f;
}

// ---------------------------------------------------------------------------
// GEMM1: E[k, n] = sum_j GT[k, j] * D16[j, n]
// CTA 128x128, BK=64, 3-stage cp.async pipeline, 8 warps of 64x32.
// 2 CTAs/SM target (regs capped at 128, smem 105KB/CTA).
// grid (K_DIM/128 = 8, LM/128 = 256), 256 threads.
// ---------------------------------------------------------------------------
__global__ __launch_bounds__(256, 2) void gemm1_kernel3() {
    extern __shared__ char sm[];

    const int tid  = threadIdx.x;
    const int warp = tid >> 5;
    const int lane = tid & 31;
    const int wm   = warp >> 2;   // 0..1  (64-row slab)
    const int wn   = warp & 3;    // 0..3  (32-col slab)
    const int mBase = blockIdx.x * BM1;
    const int nBase = blockIdx.y * BN1;

    const uint32_t smem_base = smem_u32(sm);

    wmma::fragment<wmma::accumulator, 16, 16, 16, float> acc[4][2];
#pragma unroll
    for (int i = 0; i < 4; i++)
#pragma unroll
        for (int j = 0; j < 2; j++)
            wmma::fill_fragment(acc[i][j], 0.0f);

    // Stage fill via cp.async (16B units). A: 128 rows x 8 units. B: 64 rows x 16 units.
    auto fill = [&](int s, int chunk) {
        uint32_t a_base = smem_base + s * STG1;
        uint32_t b_base = a_base + A1_BYTES;
#pragma unroll
        for (int u = tid; u < 1024; u += 256) {
            int row = u >> 3, c = u & 7;
            uint32_t dst = a_base + row * (LDA1 * 2) + c * 16;
            const void* src = &g_GT[(size_t)(mBase + row) * J_DIM + chunk * BK1 + c * 8];
            CP_ASYNC16(dst, src);
        }
#pragma unroll
        for (int u = tid; u < 1024; u += 256) {
            int row = u >> 4, c = u & 15;
            uint32_t dst = b_base + row * (LDB1 * 2) + c * 16;
            const void* src = &g_D16[(size_t)(chunk * BK1 + row) * LM + nBase + c * 8];
            CP_ASYNC16(dst, src);
        }
        CP_COMMIT();
    };

#pragma unroll
    for (int s = 0; s < NST1; s++) fill(s, s);

#pragma unroll 1
    for (int i = 0; i < NCH1; i++) {
        int s = i % NST1;
        if (i < NCH1 - 2)       CP_WAIT(2);
        else if (i == NCH1 - 2) CP_WAIT(1);
        else                    CP_WAIT(0);
        __syncthreads();

        const __half* As = reinterpret_cast<const __half*>(sm + s * STG1);
        const __half* Bs = reinterpret_cast<const __half*>(sm + s * STG1 + A1_BYTES);

#pragma unroll
        for (int kk = 0; kk < BK1 / 16; kk++) {
            wmma::fragment<wmma::matrix_a, 16, 16, 16, __half, wmma::row_major> af[4];
#pragma unroll
            for (int ii = 0; ii < 4; ii++)
                wmma::load_matrix_sync(af[ii],
                    &As[(wm * 64 + ii * 16) * LDA1 + kk * 16], LDA1);
#pragma unroll
            for (int j = 0; j < 2; j++) {
                wmma::fragment<wmma::matrix_b, 16, 16, 16, __half, wmma::row_major> bf;
                wmma::load_matrix_sync(bf,
                    &Bs[(kk * 16) * LDB1 + wn * 32 + j * 16], LDB1);
#pragma unroll
                for (int ii = 0; ii < 4; ii++)
                    wmma::mma_sync(acc[ii][j], af[ii], bf, acc[ii][j]);
            }
        }
        __syncthreads();
        if (i + NST1 < NCH1) fill(s, i + NST1);
    }

    __syncthreads();   // all warps done with smem; reuse stage 0 as epilogue staging

    // Epilogue: per-warp 16x16 staging, fp32 -> fp16, 16B stores to g_E
    float* stg = reinterpret_cast<float*>(sm) + warp * 256;
    const int r  = lane >> 1;
    const int c8 = (lane & 1) * 8;
#pragma unroll
    for (int i = 0; i < 4; i++)
#pragma unroll
        for (int j = 0; j < 2; j++) {
            wmma::store_matrix_sync(stg, acc[i][j], 16, wmma::mem_row_major);
            __syncwarp();
            const float* sp = &stg[r * 16 + c8];
            __half2 h[4];
#pragma unroll
            for (int p = 0; p < 4; p++)
                h[p] = __floats2half2_rn(sp[2 * p], sp[2 * p + 1]);
            size_t off = (size_t)(mBase + wm * 64 + i * 16 + r) * LM
                       + nBase + wn * 32 + j * 16 + c8;
            *reinterpret_cast<uint4*>(&g_E[off]) = *reinterpret_cast<uint4*>(h);
            __syncwarp();
        }
}

// ---------------------------------------------------------------------------
// GEMM2 (WMMA): out[i, m] += sum_r fp16(x[i, r]) * E[r, m]
// ---------------------------------------------------------------------------
__global__ __launch_bounds__(256) void gemm2_kernel(const float* __restrict__ X,
                                                    float* __restrict__ out) {
    __shared__ __half As[BM * LDA_S];
    __shared__ __half Bs[BK * LDB_S];
    __shared__ float  stage[8][256];

    const int tid  = threadIdx.x;
    const int warp = tid >> 5;
    const int lane = tid & 31;
    const int wm   = warp >> 1;
    const int wn   = warp & 1;
    const int mBase  = blockIdx.y * BM;
    const int kStart = blockIdx.x * SPLIT_LEN;

    wmma::fragment<wmma::accumulator, 16, 16, 16, float> acc[2][4];
#pragma unroll
    for (int i = 0; i < 2; i++)
#pragma unroll
        for (int j = 0; j < 4; j++)
            wmma::fill_fragment(acc[i][j], 0.0f);

    for (int k0 = kStart; k0 < kStart + SPLIT_LEN; k0 += BK) {
#pragma unroll
        for (int c = tid; c < 2048; c += 256) {
            int row = c >> 4, cc = c & 15;
            float2 v2 = *reinterpret_cast<const float2*>(
                &X[(size_t)(mBase + row) * R_DIM + k0 + cc * 2]);
            *reinterpret_cast<__half2*>(&As[row * LDA_S + cc * 2]) =
                __floats2half2_rn(v2.x, v2.y);
        }
#pragma unroll
        for (int c = tid; c < 512; c += 256) {
            int row = c >> 4, cc = c & 15;
            *reinterpret_cast<uint4*>(&Bs[row * LDB_S + cc * 8]) =
                *reinterpret_cast<const uint4*>(&g_E[(size_t)(k0 + row) * M_DIM + cc * 8]);
        }
        __syncthreads();
#pragma unroll
        for (int kk = 0; kk < BK; kk += 16) {
            wmma::fragment<wmma::matrix_a, 16, 16, 16, __half, wmma::row_major> af[2];
            wmma::fragment<wmma::matrix_b, 16, 16, 16, __half, wmma::row_major> bf[4];
#pragma unroll
            for (int i = 0; i < 2; i++)
                wmma::load_matrix_sync(af[i], &As[(wm * 32 + i * 16) * LDA_S + kk], LDA_S);
#pragma unroll
            for (int j = 0; j < 4; j++)
                wmma::load_matrix_sync(bf[j], &Bs[kk * LDB_S + wn * 64 + j * 16], LDB_S);
#pragma unroll
            for (int i = 0; i < 2; i++)
#pragma unroll
                for (int j = 0; j < 4; j++)
                    wmma::mma_sync(acc[i][j], af[i], bf[j], acc[i][j]);
        }
        __syncthreads();
    }

    const int r  = lane >> 1;
    const int c8 = (lane & 1) * 8;
#pragma unroll
    for (int i = 0; i < 2; i++)
#pragma unroll
        for (int j = 0; j < 4; j++) {
            wmma::store_matrix_sync(stage[warp], acc[i][j], 16, wmma::mem_row_major);
            __syncwarp();
            const float* sp = &stage[warp][r * 16 + c8];
            int gm = mBase + wm * 32 + i * 16 + r;
            int gn = wn * 64 + j * 16 + c8;
#pragma unroll
            for (int t = 0; t < 8; t++)
                atomicAdd(&out[gm * M_DIM + gn + t], sp[t]);
            __syncwarp();
        }
}

// ---------------------------------------------------------------------------
// Launch
// ---------------------------------------------------------------------------
extern "C" void kernel_launch(void* const* d_in, const int* in_sizes, int n_in,
                              void* d_out, int out_size) {
    const float* x = (const float*)d_in[0];   // (256, 1024, 256)
    const float* G = (const float*)d_in[1];   // (1024, 1024)
    const float* v = (const float*)d_in[2];   // (1024, 256, 128)
    const float* w = (const float*)d_in[3];   // (1024, 256, 128)
    float* out = (float*)d_out;               // (256, 128)

    // Idempotent, non-stream API call: capture-legal, no static guards.
    cudaFuncSetAttribute(gemm1_kernel3,
                         cudaFuncAttributeMaxDynamicSharedMemorySize, SMEM1);

    conv_GT_kernel<<<dim3(32, 32), dim3(32, 32)>>>(G);
    conv_D_kernel<<<(J_DIM * (size_t)LM) / (4 * 256), 256>>>(v, w);
    zero_kernel<<<(BATCH * M_DIM) / 256, 256>>>(out);
    gemm1_kernel3<<<dim3(K_DIM / BM1, LM / BN1), 256, SMEM1>>>();
    gemm2_kernel<<<dim3(NSPLIT, BATCH / BM), 256>>>(x, out);
}

// round 12
// speedup vs baseline: 1.2730x; 1.0829x over previous
#include <cuda_runtime.h>
#include <cuda_fp16.h>
#include <mma.h>
#include <cstdint>

using namespace nvcuda;

// Problem dims
#define BATCH 256
#define J_DIM 1024            // neurons (reduction of GEMM1)
#define K_DIM 1024            // n_feat  (M of GEMM1)
#define L_DIM 256             // in_dim
#define M_DIM 128             // out_dim (N of GEMM2)
#define LM    (L_DIM * M_DIM) // 32768   (N of GEMM1)
#define R_DIM (K_DIM * L_DIM) // 262144  (reduction of GEMM2)

// GEMM2 tiling (pipelined)
#define BM 128
#define BK2 32
#define LDA_S 40                        // halves per Xf16 row (80 B)
#define LDE2 136                        // halves per E row (272 B)
#define LDXF 36                         // floats per Xf32 row (144 B)
#define XF32_BYTES (BM * LDXF * 4)      // 18432
#define E2_BYTES (BK2 * LDE2 * 2)       // 8704
#define STG2 (XF32_BYTES + E2_BYTES)    // 27136
#define NST2 3
#define XF16_BYTES (BM * LDA_S * 2)     // 10240
#define SMEM2 (NST2 * STG2 + XF16_BYTES) // 91648 (x2 CTAs = 183KB <= 228KB)
#define NSPLIT 128
#define SPLIT_LEN (R_DIM / NSPLIT)      // 2048
#define NCH2 (SPLIT_LEN / BK2)          // 64

// GEMM1 tiling: CTA 128x128x64, 8 warps of 64x32, 2 CTAs/SM
#define BM1 128
#define BN1 128
#define BK1 64
#define LDA1 72                        // halves (144 B rows)
#define LDB1 136                       // halves (272 B rows)
#define NST1 3
#define A1_BYTES (BM1 * LDA1 * 2)      // 18432
#define B1_BYTES (BK1 * LDB1 * 2)      // 17408
#define STG1 (A1_BYTES + B1_BYTES)     // 35840
#define SMEM1 (NST1 * STG1)            // 107520 (x2 CTAs = 215KB <= 228KB)
#define NCH1 (J_DIM / BK1)             // 16

// Scratch (static device globals — no allocation APIs allowed)
__device__ __half g_GT[(size_t)K_DIM * J_DIM];   //  2 MB : G^T fp16, (k, j)
__device__ __half g_D16[(size_t)J_DIM * LM];     // 64 MB : (v-w) fp16, (j, lm)
__device__ __half g_E[(size_t)K_DIM * LM];       // 64 MB : E fp16, (r, m)

// ---------------------------------------------------------------------------
// Helpers
// ---------------------------------------------------------------------------
__device__ __forceinline__ uint32_t smem_u32(const void* p) {
    uint32_t a;
    asm("{ .reg .u64 t; cvta.to.shared.u64 t, %1; cvt.u32.u64 %0, t; }" : "=r"(a) : "l"(p));
    return a;
}
#define CP_ASYNC16(dst, src) \
    asm volatile("cp.async.cg.shared.global [%0], [%1], 16;" :: "r"(dst), "l"(src))
#define CP_COMMIT() asm volatile("cp.async.commit_group;" ::: "memory")
#define CP_WAIT(n)  asm volatile("cp.async.wait_group %0;" :: "n"(n) : "memory")

// ---------------------------------------------------------------------------
// Convert kernels
// ---------------------------------------------------------------------------

// G (j,k) fp32 -> g_GT (k,j) fp16
__global__ void conv_GT_kernel(const float* __restrict__ G) {
    __shared__ float t[32][33];
    int jx = blockIdx.y * 32 + threadIdx.y;
    int kx = blockIdx.x * 32 + threadIdx.x;
    t[threadIdx.y][threadIdx.x] = G[jx * K_DIM + kx];
    __syncthreads();
    int ko = blockIdx.x * 32 + threadIdx.y;
    int jo = blockIdx.y * 32 + threadIdx.x;
    g_GT[(size_t)ko * J_DIM + jo] = __float2half(t[threadIdx.x][threadIdx.y]);
}

// g_D16 = fp16(v - w), elementwise, 4 elems/thread (streaming, coalesced)
__global__ void conv_D_kernel(const float* __restrict__ v, const float* __restrict__ w) {
    size_t i = (size_t)blockIdx.x * blockDim.x + threadIdx.x;  // float4 units
    float4 a = reinterpret_cast<const float4*>(v)[i];
    float4 b = reinterpret_cast<const float4*>(w)[i];
    __half2 lo = __floats2half2_rn(a.x - b.x, a.y - b.y);
    __half2 hi = __floats2half2_rn(a.z - b.z, a.w - b.w);
    __half2* dst = reinterpret_cast<__half2*>(&g_D16[i * 4]);
    dst[0] = lo;
    dst[1] = hi;
}

__global__ void zero_kernel(float* __restrict__ o) {
    int i = blockIdx.x * 256 + threadIdx.x;
    o[i] = 0.0f;
}

// ---------------------------------------------------------------------------
// GEMM1: E[k, n] = sum_j GT[k, j] * D16[j, n]
// CTA 128x128, BK=64, 3-stage cp.async, ONE barrier per chunk
// (fill-before-compute: slot (i-1)%3 is provably free after the barrier).
// grid (8, 256), 256 threads, 2 CTAs/SM.
// ---------------------------------------------------------------------------
__global__ __launch_bounds__(256, 2) void gemm1_kernel4() {
    extern __shared__ char sm[];

    const int tid  = threadIdx.x;
    const int warp = tid >> 5;
    const int lane = tid & 31;
    const int wm   = warp >> 2;   // 0..1  (64-row slab)
    const int wn   = warp & 3;    // 0..3  (32-col slab)
    const int mBase = blockIdx.x * BM1;
    const int nBase = blockIdx.y * BN1;

    const uint32_t smem_base = smem_u32(sm);

    wmma::fragment<wmma::accumulator, 16, 16, 16, float> acc[4][2];
#pragma unroll
    for (int i = 0; i < 4; i++)
#pragma unroll
        for (int j = 0; j < 2; j++)
            wmma::fill_fragment(acc[i][j], 0.0f);

    auto fill = [&](int s, int chunk) {
        uint32_t a_base = smem_base + s * STG1;
        uint32_t b_base = a_base + A1_BYTES;
#pragma unroll
        for (int u = tid; u < 1024; u += 256) {
            int row = u >> 3, c = u & 7;
            uint32_t dst = a_base + row * (LDA1 * 2) + c * 16;
            const void* src = &g_GT[(size_t)(mBase + row) * J_DIM + chunk * BK1 + c * 8];
            CP_ASYNC16(dst, src);
        }
#pragma unroll
        for (int u = tid; u < 1024; u += 256) {
            int row = u >> 4, c = u & 15;
            uint32_t dst = b_base + row * (LDB1 * 2) + c * 16;
            const void* src = &g_D16[(size_t)(chunk * BK1 + row) * LM + nBase + c * 8];
            CP_ASYNC16(dst, src);
        }
        CP_COMMIT();
    };

#pragma unroll
    for (int s = 0; s < NST1; s++) fill(s, s);

#pragma unroll 1
    for (int i = 0; i < NCH1; i++) {
        const int s = i % NST1;
        if (i < NCH1 - 1) CP_WAIT(1);
        else              CP_WAIT(0);
        __syncthreads();   // chunk i resident; all warps done with chunk i-1

        if (i >= 1 && i + 2 < NCH1)
            fill((i + 2) % NST1, i + 2);   // overwrite slot (i-1)%3, now free

        const __half* As = reinterpret_cast<const __half*>(sm + s * STG1);
        const __half* Bs = reinterpret_cast<const __half*>(sm + s * STG1 + A1_BYTES);

#pragma unroll
        for (int kk = 0; kk < BK1 / 16; kk++) {
            wmma::fragment<wmma::matrix_a, 16, 16, 16, __half, wmma::row_major> af[4];
#pragma unroll
            for (int ii = 0; ii < 4; ii++)
                wmma::load_matrix_sync(af[ii],
                    &As[(wm * 64 + ii * 16) * LDA1 + kk * 16], LDA1);
#pragma unroll
            for (int j = 0; j < 2; j++) {
                wmma::fragment<wmma::matrix_b, 16, 16, 16, __half, wmma::row_major> bf;
                wmma::load_matrix_sync(bf,
                    &Bs[(kk * 16) * LDB1 + wn * 32 + j * 16], LDB1);
#pragma unroll
                for (int ii = 0; ii < 4; ii++)
                    wmma::mma_sync(acc[ii][j], af[ii], bf, acc[ii][j]);
            }
        }
    }

    __syncthreads();   // smem free for epilogue staging

    float* stg = reinterpret_cast<float*>(sm) + warp * 256;
    const int r  = lane >> 1;
    const int c8 = (lane & 1) * 8;
#pragma unroll
    for (int i = 0; i < 4; i++)
#pragma unroll
        for (int j = 0; j < 2; j++) {
            wmma::store_matrix_sync(stg, acc[i][j], 16, wmma::mem_row_major);
            __syncwarp();
            const float* sp = &stg[r * 16 + c8];
            __half2 h[4];
#pragma unroll
            for (int p = 0; p < 4; p++)
                h[p] = __floats2half2_rn(sp[2 * p], sp[2 * p + 1]);
            size_t off = (size_t)(mBase + wm * 64 + i * 16 + r) * LM
                       + nBase + wn * 32 + j * 16 + c8;
            *reinterpret_cast<uint4*>(&g_E[off]) = *reinterpret_cast<uint4*>(h);
            __syncwarp();
        }
}

// ---------------------------------------------------------------------------
// GEMM2: out[i, m] += sum_r fp16(x[i, r]) * E[r, m]
// 3-stage cp.async pipeline: X staged fp32, converted to fp16 in smem.
// grid (NSPLIT, BATCH/BM = 2), 256 threads (8 warps, 4x2 of 32x64).
// ---------------------------------------------------------------------------
__global__ __launch_bounds__(256, 2) void gemm2_kernel2(const float* __restrict__ X,
                                                        float* __restrict__ out) {
    extern __shared__ char sm[];

    const int tid  = threadIdx.x;
    const int warp = tid >> 5;
    const int lane = tid & 31;
    const int wm   = warp >> 1;   // 0..3  (32-row slab)
    const int wn   = warp & 1;    // 0..1  (64-col slab)
    const int mBase  = blockIdx.y * BM;
    const int kStart = blockIdx.x * SPLIT_LEN;

    const uint32_t smem_base = smem_u32(sm);
    __half* xh = reinterpret_cast<__half*>(sm + NST2 * STG2);

    wmma::fragment<wmma::accumulator, 16, 16, 16, float> acc[2][4];
#pragma unroll
    for (int i = 0; i < 2; i++)
#pragma unroll
        for (int j = 0; j < 4; j++)
            wmma::fill_fragment(acc[i][j], 0.0f);

    auto fill = [&](int s, int chunk) {
        uint32_t x_base = smem_base + s * STG2;
        uint32_t e_base = x_base + XF32_BYTES;
        int k0 = kStart + chunk * BK2;
#pragma unroll
        for (int u = tid; u < 1024; u += 256) {       // X: 128 rows x 8 x 16B (fp32)
            int row = u >> 3, c = u & 7;
            uint32_t dst = x_base + row * (LDXF * 4) + c * 16;
            const void* src = &X[(size_t)(mBase + row) * R_DIM + k0 + c * 4];
            CP_ASYNC16(dst, src);
        }
#pragma unroll
        for (int u = tid; u < 512; u += 256) {        // E: 32 rows x 16 x 16B (fp16)
            int row = u >> 4, c = u & 15;
            uint32_t dst = e_base + row * (LDE2 * 2) + c * 16;
            const void* src = &g_E[(size_t)(k0 + row) * M_DIM + c * 8];
            CP_ASYNC16(dst, src);
        }
        CP_COMMIT();
    };

#pragma unroll
    for (int s = 0; s < NST2; s++) fill(s, s);

#pragma unroll 1
    for (int i = 0; i < NCH2; i++) {
        const int s = i % NST2;
        if (i < NCH2 - 1) CP_WAIT(1);
        else              CP_WAIT(0);
        __syncthreads();   // chunk i resident; prior iter fully consumed

        if (i >= 1 && i + 2 < NCH2)
            fill((i + 2) % NST2, i + 2);

        // Convert X fp32 (slot s) -> fp16 (shared single buffer)
        {
            const float* xf = reinterpret_cast<const float*>(sm + s * STG2);
#pragma unroll
            for (int u = tid; u < 512; u += 256) {    // 128 rows x 4 x (8 halves)
                int row = u >> 2, q = u & 3;
                float4 a = *reinterpret_cast<const float4*>(&xf[row * LDXF + q * 8]);
                float4 b = *reinterpret_cast<const float4*>(&xf[row * LDXF + q * 8 + 4]);
                __half2 h[4];
                h[0] = __floats2half2_rn(a.x, a.y);
                h[1] = __floats2half2_rn(a.z, a.w);
                h[2] = __floats2half2_rn(b.x, b.y);
                h[3] = __floats2half2_rn(b.z, b.w);
                *reinterpret_cast<uint4*>(&xh[row * LDA_S + q * 8]) =
                    *reinterpret_cast<uint4*>(h);
            }
        }
        __syncthreads();   // converted tile visible to all warps

        const __half* Bs = reinterpret_cast<const __half*>(sm + s * STG2 + XF32_BYTES);
#pragma unroll
        for (int kk = 0; kk < BK2; kk += 16) {
            wmma::fragment<wmma::matrix_a, 16, 16, 16, __half, wmma::row_major> af[2];
            wmma::fragment<wmma::matrix_b, 16, 16, 16, __half, wmma::row_major> bf[4];
#pragma unroll
            for (int ii = 0; ii < 2; ii++)
                wmma::load_matrix_sync(af[ii], &xh[(wm * 32 + ii * 16) * LDA_S + kk], LDA_S);
#pragma unroll
            for (int j = 0; j < 4; j++)
                wmma::load_matrix_sync(bf[j], &Bs[kk * LDE2 + wn * 64 + j * 16], LDE2);
#pragma unroll
            for (int ii = 0; ii < 2; ii++)
#pragma unroll
                for (int j = 0; j < 4; j++)
                    wmma::mma_sync(acc[ii][j], af[ii], bf[j], acc[ii][j]);
        }
    }

    __syncthreads();   // smem free for epilogue staging

    float* stg = reinterpret_cast<float*>(sm) + warp * 256;
    const int r  = lane >> 1;
    const int c8 = (lane & 1) * 8;
#pragma unroll
    for (int i = 0; i < 2; i++)
#pragma unroll
        for (int j = 0; j < 4; j++) {
            wmma::store_matrix_sync(stg, acc[i][j], 16, wmma::mem_row_major);
            __syncwarp();
            const float* sp = &stg[r * 16 + c8];
            int gm = mBase + wm * 32 + i * 16 + r;
            int gn = wn * 64 + j * 16 + c8;
#pragma unroll
            for (int t = 0; t < 8; t++)
                atomicAdd(&out[gm * M_DIM + gn + t], sp[t]);
            __syncwarp();
        }
}

// ---------------------------------------------------------------------------
// Launch
// ---------------------------------------------------------------------------
extern "C" void kernel_launch(void* const* d_in, const int* in_sizes, int n_in,
                              void* d_out, int out_size) {
    const float* x = (const float*)d_in[0];   // (256, 1024, 256)
    const float* G = (const float*)d_in[1];   // (1024, 1024)
    const float* v = (const float*)d_in[2];   // (1024, 256, 128)
    const float* w = (const float*)d_in[3];   // (1024, 256, 128)
    float* out = (float*)d_out;               // (256, 128)

    // Idempotent, non-stream API calls: capture-legal, no static guards.
    cudaFuncSetAttribute(gemm1_kernel4,
                         cudaFuncAttributeMaxDynamicSharedMemorySize, SMEM1);
    cudaFuncSetAttribute(gemm2_kernel2,
                         cudaFuncAttributeMaxDynamicSharedMemorySize, SMEM2);

    conv_GT_kernel<<<dim3(32, 32), dim3(32, 32)>>>(G);
    conv_D_kernel<<<(J_DIM * (size_t)LM) / (4 * 256), 256>>>(v, w);
    zero_kernel<<<(BATCH * M_DIM) / 256, 256>>>(out);
    gemm1_kernel4<<<dim3(K_DIM / BM1, LM / BN1), 256, SMEM1>>>();
    gemm2_kernel2<<<dim3(NSPLIT, BATCH / BM), 256, SMEM2>>>(x, out);
}

// round 13
// speedup vs baseline: 1.2934x; 1.0160x over previous
#include <cuda_runtime.h>
#include <cuda_fp16.h>
#include <mma.h>
#include <cstdint>

using namespace nvcuda;

// Problem dims
#define BATCH 256
#define J_DIM 1024            // neurons (reduction of GEMM1)
#define K_DIM 1024            // n_feat  (M of GEMM1)
#define L_DIM 256             // in_dim
#define M_DIM 128             // out_dim (N of GEMM2)
#define LM    (L_DIM * M_DIM) // 32768   (N of GEMM1)
#define R_DIM (K_DIM * L_DIM) // 262144  (reduction of GEMM2)

// GEMM2 tiling (pipelined)
#define BM 128
#define BK2 32
#define LDA_S 40                        // halves per Xf16 row (80 B)
#define LDE2 136                        // halves per E row (272 B)
#define LDXF 36                         // floats per Xf32 row (144 B)
#define XF32_BYTES (BM * LDXF * 4)      // 18432
#define E2_BYTES (BK2 * LDE2 * 2)       // 8704
#define STG2 (XF32_BYTES + E2_BYTES)    // 27136
#define NST2 3
#define XF16_BYTES (BM * LDA_S * 2)     // 10240
#define SMEM2 (NST2 * STG2 + XF16_BYTES) // 91648 (x2 CTAs = 183KB <= 228KB)
#define NSPLIT 128
#define SPLIT_LEN (R_DIM / NSPLIT)      // 2048
#define NCH2 (SPLIT_LEN / BK2)          // 64

// GEMM1 tiling: CTA 128x128x64, 4 warps of 64x64, 128 threads, 2 CTAs/SM
#define BM1 128
#define BN1 128
#define BK1 64
#define T1_THREADS 128
#define LDA1 72                        // halves (144 B rows)
#define LDB1 136                       // halves (272 B rows)
#define NST1 3
#define A1_BYTES (BM1 * LDA1 * 2)      // 18432
#define B1_BYTES (BK1 * LDB1 * 2)      // 17408
#define STG1 (A1_BYTES + B1_BYTES)     // 35840
#define SMEM1 (NST1 * STG1)            // 107520 (x2 CTAs = 215KB <= 228KB)
#define NCH1 (J_DIM / BK1)             // 16

// Scratch (static device globals — no allocation APIs allowed)
__device__ __half g_GT[(size_t)K_DIM * J_DIM];   //  2 MB : G^T fp16, (k, j)
__device__ __half g_D16[(size_t)J_DIM * LM];     // 64 MB : (v-w) fp16, (j, lm)
__device__ __half g_E[(size_t)K_DIM * LM];       // 64 MB : E fp16, (r, m)

// ---------------------------------------------------------------------------
// Helpers
// ---------------------------------------------------------------------------
__device__ __forceinline__ uint32_t smem_u32(const void* p) {
    uint32_t a;
    asm("{ .reg .u64 t; cvta.to.shared.u64 t, %1; cvt.u32.u64 %0, t; }" : "=r"(a) : "l"(p));
    return a;
}
#define CP_ASYNC16(dst, src) \
    asm volatile("cp.async.cg.shared.global [%0], [%1], 16;" :: "r"(dst), "l"(src))
#define CP_COMMIT() asm volatile("cp.async.commit_group;" ::: "memory")
#define CP_WAIT(n)  asm volatile("cp.async.wait_group %0;" :: "n"(n) : "memory")

// ---------------------------------------------------------------------------
// Convert kernels
// ---------------------------------------------------------------------------

// G (j,k) fp32 -> g_GT (k,j) fp16
__global__ void conv_GT_kernel(const float* __restrict__ G) {
    __shared__ float t[32][33];
    int jx = blockIdx.y * 32 + threadIdx.y;
    int kx = blockIdx.x * 32 + threadIdx.x;
    t[threadIdx.y][threadIdx.x] = G[jx * K_DIM + kx];
    __syncthreads();
    int ko = blockIdx.x * 32 + threadIdx.y;
    int jo = blockIdx.y * 32 + threadIdx.x;
    g_GT[(size_t)ko * J_DIM + jo] = __float2half(t[threadIdx.x][threadIdx.y]);
}

// g_D16 = fp16(v - w), elementwise, 4 elems/thread (streaming, coalesced)
__global__ void conv_D_kernel(const float* __restrict__ v, const float* __restrict__ w) {
    size_t i = (size_t)blockIdx.x * blockDim.x + threadIdx.x;  // float4 units
    float4 a = reinterpret_cast<const float4*>(v)[i];
    float4 b = reinterpret_cast<const float4*>(w)[i];
    __half2 lo = __floats2half2_rn(a.x - b.x, a.y - b.y);
    __half2 hi = __floats2half2_rn(a.z - b.z, a.w - b.w);
    __half2* dst = reinterpret_cast<__half2*>(&g_D16[i * 4]);
    dst[0] = lo;
    dst[1] = hi;
}

__global__ void zero_kernel(float* __restrict__ o) {
    int i = blockIdx.x * 256 + threadIdx.x;
    o[i] = 0.0f;
}

// ---------------------------------------------------------------------------
// GEMM1: E[k, n] = sum_j GT[k, j] * D16[j, n]
// CTA 128x128, BK=64, 3-stage cp.async, one barrier per chunk.
// 128 threads: 4 warps of 64x64 (halves smem fragment re-reads vs 64x32).
// 2 CTAs/SM (24K regs + 105KB smem per CTA). grid (8, 256).
// ---------------------------------------------------------------------------
__global__ __launch_bounds__(T1_THREADS, 2) void gemm1_kernel5() {
    extern __shared__ char sm[];

    const int tid  = threadIdx.x;
    const int warp = tid >> 5;
    const int lane = tid & 31;
    const int wm   = warp >> 1;   // 0..1  (64-row slab)
    const int wn   = warp & 1;    // 0..1  (64-col slab)
    const int mBase = blockIdx.x * BM1;
    const int nBase = blockIdx.y * BN1;

    const uint32_t smem_base = smem_u32(sm);

    wmma::fragment<wmma::accumulator, 16, 16, 16, float> acc[4][4];
#pragma unroll
    for (int i = 0; i < 4; i++)
#pragma unroll
        for (int j = 0; j < 4; j++)
            wmma::fill_fragment(acc[i][j], 0.0f);

    auto fill = [&](int s, int chunk) {
        uint32_t a_base = smem_base + s * STG1;
        uint32_t b_base = a_base + A1_BYTES;
#pragma unroll
        for (int u = tid; u < 1024; u += T1_THREADS) {
            int row = u >> 3, c = u & 7;
            uint32_t dst = a_base + row * (LDA1 * 2) + c * 16;
            const void* src = &g_GT[(size_t)(mBase + row) * J_DIM + chunk * BK1 + c * 8];
            CP_ASYNC16(dst, src);
        }
#pragma unroll
        for (int u = tid; u < 1024; u += T1_THREADS) {
            int row = u >> 4, c = u & 15;
            uint32_t dst = b_base + row * (LDB1 * 2) + c * 16;
            const void* src = &g_D16[(size_t)(chunk * BK1 + row) * LM + nBase + c * 8];
            CP_ASYNC16(dst, src);
        }
        CP_COMMIT();
    };

#pragma unroll
    for (int s = 0; s < NST1; s++) fill(s, s);

#pragma unroll 1
    for (int i = 0; i < NCH1; i++) {
        const int s = i % NST1;
        if (i < NCH1 - 1) CP_WAIT(1);
        else              CP_WAIT(0);
        __syncthreads();   // chunk i resident; all warps done with chunk i-1

        if (i >= 1 && i + 2 < NCH1)
            fill((i + 2) % NST1, i + 2);   // overwrite slot (i-1)%3, now free

        const __half* As = reinterpret_cast<const __half*>(sm + s * STG1);
        const __half* Bs = reinterpret_cast<const __half*>(sm + s * STG1 + A1_BYTES);

#pragma unroll
        for (int kk = 0; kk < BK1 / 16; kk++) {
            wmma::fragment<wmma::matrix_a, 16, 16, 16, __half, wmma::row_major> af[4];
            wmma::fragment<wmma::matrix_b, 16, 16, 16, __half, wmma::row_major> bf[4];
#pragma unroll
            for (int ii = 0; ii < 4; ii++)
                wmma::load_matrix_sync(af[ii],
                    &As[(wm * 64 + ii * 16) * LDA1 + kk * 16], LDA1);
#pragma unroll
            for (int j = 0; j < 4; j++)
                wmma::load_matrix_sync(bf[j],
                    &Bs[(kk * 16) * LDB1 + wn * 64 + j * 16], LDB1);
#pragma unroll
            for (int ii = 0; ii < 4; ii++)
#pragma unroll
                for (int j = 0; j < 4; j++)
                    wmma::mma_sync(acc[ii][j], af[ii], bf[j], acc[ii][j]);
        }
    }

    __syncthreads();   // smem free for epilogue staging

    float* stg = reinterpret_cast<float*>(sm) + warp * 256;
    const int r  = lane >> 1;
    const int c8 = (lane & 1) * 8;
#pragma unroll
    for (int i = 0; i < 4; i++)
#pragma unroll
        for (int j = 0; j < 4; j++) {
            wmma::store_matrix_sync(stg, acc[i][j], 16, wmma::mem_row_major);
            __syncwarp();
            const float* sp = &stg[r * 16 + c8];
            __half2 h[4];
#pragma unroll
            for (int p = 0; p < 4; p++)
                h[p] = __floats2half2_rn(sp[2 * p], sp[2 * p + 1]);
            size_t off = (size_t)(mBase + wm * 64 + i * 16 + r) * LM
                       + nBase + wn * 64 + j * 16 + c8;
            *reinterpret_cast<uint4*>(&g_E[off]) = *reinterpret_cast<uint4*>(h);
            __syncwarp();
        }
}

// ---------------------------------------------------------------------------
// GEMM2: out[i, m] += sum_r fp16(x[i, r]) * E[r, m]
// 3-stage cp.async pipeline: X staged fp32, converted to fp16 in smem.
// grid (NSPLIT, BATCH/BM = 2), 256 threads (8 warps, 4x2 of 32x64).
// ---------------------------------------------------------------------------
__global__ __launch_bounds__(256, 2) void gemm2_kernel2(const float* __restrict__ X,
                                                        float* __restrict__ out) {
    extern __shared__ char sm[];

    const int tid  = threadIdx.x;
    const int warp = tid >> 5;
    const int lane = tid & 31;
    const int wm   = warp >> 1;   // 0..3  (32-row slab)
    const int wn   = warp & 1;    // 0..1  (64-col slab)
    const int mBase  = blockIdx.y * BM;
    const int kStart = blockIdx.x * SPLIT_LEN;

    const uint32_t smem_base = smem_u32(sm);
    __half* xh = reinterpret_cast<__half*>(sm + NST2 * STG2);

    wmma::fragment<wmma::accumulator, 16, 16, 16, float> acc[2][4];
#pragma unroll
    for (int i = 0; i < 2; i++)
#pragma unroll
        for (int j = 0; j < 4; j++)
            wmma::fill_fragment(acc[i][j], 0.0f);

    auto fill = [&](int s, int chunk) {
        uint32_t x_base = smem_base + s * STG2;
        uint32_t e_base = x_base + XF32_BYTES;
        int k0 = kStart + chunk * BK2;
#pragma unroll
        for (int u = tid; u < 1024; u += 256) {       // X: 128 rows x 8 x 16B (fp32)
            int row = u >> 3, c = u & 7;
            uint32_t dst = x_base + row * (LDXF * 4) + c * 16;
            const void* src = &X[(size_t)(mBase + row) * R_DIM + k0 + c * 4];
            CP_ASYNC16(dst, src);
        }
#pragma unroll
        for (int u = tid; u < 512; u += 256) {        // E: 32 rows x 16 x 16B (fp16)
            int row = u >> 4, c = u & 15;
            uint32_t dst = e_base + row * (LDE2 * 2) + c * 16;
            const void* src = &g_E[(size_t)(k0 + row) * M_DIM + c * 8];
            CP_ASYNC16(dst, src);
        }
        CP_COMMIT();
    };

#pragma unroll
    for (int s = 0; s < NST2; s++) fill(s, s);

#pragma unroll 1
    for (int i = 0; i < NCH2; i++) {
        const int s = i % NST2;
        if (i < NCH2 - 1) CP_WAIT(1);
        else              CP_WAIT(0);
        __syncthreads();   // chunk i resident; prior iter fully consumed

        if (i >= 1 && i + 2 < NCH2)
            fill((i + 2) % NST2, i + 2);

        // Convert X fp32 (slot s) -> fp16 (shared single buffer)
        {
            const float* xf = reinterpret_cast<const float*>(sm + s * STG2);
#pragma unroll
            for (int u = tid; u < 512; u += 256) {    // 128 rows x 4 x (8 halves)
                int row = u >> 2, q = u & 3;
                float4 a = *reinterpret_cast<const float4*>(&xf[row * LDXF + q * 8]);
                float4 b = *reinterpret_cast<const float4*>(&xf[row * LDXF + q * 8 + 4]);
                __half2 h[4];
                h[0] = __floats2half2_rn(a.x, a.y);
                h[1] = __floats2half2_rn(a.z, a.w);
                h[2] = __floats2half2_rn(b.x, b.y);
                h[3] = __floats2half2_rn(b.z, b.w);
                *reinterpret_cast<uint4*>(&xh[row * LDA_S + q * 8]) =
                    *reinterpret_cast<uint4*>(h);
            }
        }
        __syncthreads();   // converted tile visible to all warps

        const __half* Bs = reinterpret_cast<const __half*>(sm + s * STG2 + XF32_BYTES);
#pragma unroll
        for (int kk = 0; kk < BK2; kk += 16) {
            wmma::fragment<wmma::matrix_a, 16, 16, 16, __half, wmma::row_major> af[2];
            wmma::fragment<wmma::matrix_b, 16, 16, 16, __half, wmma::row_major> bf[4];
#pragma unroll
            for (int ii = 0; ii < 2; ii++)
                wmma::load_matrix_sync(af[ii], &xh[(wm * 32 + ii * 16) * LDA_S + kk], LDA_S);
#pragma unroll
            for (int j = 0; j < 4; j++)
                wmma::load_matrix_sync(bf[j], &Bs[kk * LDE2 + wn * 64 + j * 16], LDE2);
#pragma unroll
            for (int ii = 0; ii < 2; ii++)
#pragma unroll
                for (int j = 0; j < 4; j++)
                    wmma::mma_sync(acc[ii][j], af[ii], bf[j], acc[ii][j]);
        }
    }

    __syncthreads();   // smem free for epilogue staging

    float* stg = reinterpret_cast<float*>(sm) + warp * 256;
    const int r  = lane >> 1;
    const int c8 = (lane & 1) * 8;
#pragma unroll
    for (int i = 0; i < 2; i++)
#pragma unroll
        for (int j = 0; j < 4; j++) {
            wmma::store_matrix_sync(stg, acc[i][j], 16, wmma::mem_row_major);
            __syncwarp();
            const float* sp = &stg[r * 16 + c8];
            int gm = mBase + wm * 32 + i * 16 + r;
            int gn = wn * 64 + j * 16 + c8;
#pragma unroll
            for (int t = 0; t < 8; t++)
                atomicAdd(&out[gm * M_DIM + gn + t], sp[t]);
            __syncwarp();
        }
}

// ---------------------------------------------------------------------------
// Launch
// ---------------------------------------------------------------------------
extern "C" void kernel_launch(void* const* d_in, const int* in_sizes, int n_in,
                              void* d_out, int out_size) {
    const float* x = (const float*)d_in[0];   // (256, 1024, 256)
    const float* G = (const float*)d_in[1];   // (1024, 1024)
    const float* v = (const float*)d_in[2];   // (1024, 256, 128)
    const float* w = (const float*)d_in[3];   // (1024, 256, 128)
    float* out = (float*)d_out;               // (256, 128)

    // Idempotent, non-stream API calls: capture-legal, no static guards.
    cudaFuncSetAttribute(gemm1_kernel5,
                         cudaFuncAttributeMaxDynamicSharedMemorySize, SMEM1);
    cudaFuncSetAttribute(gemm2_kernel2,
                         cudaFuncAttributeMaxDynamicSharedMemorySize, SMEM2);

    conv_GT_kernel<<<dim3(32, 32), dim3(32, 32)>>>(G);
    conv_D_kernel<<<(J_DIM * (size_t)LM) / (4 * 256), 256>>>(v, w);
    zero_kernel<<<(BATCH * M_DIM) / 256, 256>>>(out);
    gemm1_kernel5<<<dim3(K_DIM / BM1, LM / BN1), T1_THREADS, SMEM1>>>();
    gemm2_kernel2<<<dim3(NSPLIT, BATCH / BM), 256, SMEM2>>>(x, out);
}